// round 15
// baseline (speedup 1.0000x reference)
#include <cuda_runtime.h>
#include <cstdint>
#include <cstddef>

// Problem constants (fixed shapes)
#define HDIM   2048
#define IDIM   1024
#define TTOK   4096   // B*S
#define NEXP   8      // routed experts
#define NTOT   12     // routed + zero
#define RSCALE 1.5f

#define BK         32          // k-chunk per pipeline stage
#define RS         36          // smem row stride in floats (144 B) -> conflict-free
#define STG_BYTES  36864u
#define SM_BYTES   (1024 + 3 * 36864)   // header + 3 stages = 111616 B

// ---------------- device scratch (no allocations allowed) ----------------
__device__ int   g_cnt[NEXP];
__device__ int   g_tok[NEXP * TTOK];
__device__ float g_wgt[NEXP * TTOK];
__device__ float g_xr[(size_t)TTOK * HDIM];           // 32 MB tf32-rounded x
__device__ float g_act[(size_t)NEXP * TTOK * IDIM];   // 128 MB fp32 scratch

// ---------------- helpers -------------------------------------------------
static __device__ __forceinline__ uint32_t smem_u32(const void* p) {
    uint32_t a;
    asm("{ .reg .u64 t; cvta.to.shared.u64 t, %1; cvt.u32.u64 %0, t; }"
        : "=r"(a) : "l"(p));
    return a;
}
static __device__ __forceinline__ uint32_t to_tf32(float f) {
    uint32_t u;
    asm("cvt.rna.tf32.f32 %0, %1;" : "=r"(u) : "f"(f));
    return u;
}
static __device__ __forceinline__ uint32_t rnd_bits(uint32_t bits) {
    uint32_t u;
    asm("cvt.rna.tf32.f32 %0, %1;" : "=r"(u) : "f"(__uint_as_float(bits)));
    return u;
}
// d += a(16x8 tf32, row) * b(8x8 tf32, col)
static __device__ __forceinline__ void mma_tf32(float* d, const uint32_t* a,
                                                const uint32_t* b) {
    asm volatile(
        "mma.sync.aligned.m16n8k8.row.col.f32.tf32.tf32.f32 "
        "{%0,%1,%2,%3}, {%4,%5,%6,%7}, {%8,%9}, {%0,%1,%2,%3};"
        : "+f"(d[0]), "+f"(d[1]), "+f"(d[2]), "+f"(d[3])
        : "r"(a[0]), "r"(a[1]), "r"(a[2]), "r"(a[3]), "r"(b[0]), "r"(b[1]));
}
// one ldmatrix.x4: four 8x4-tf32 tiles (presented as 8x8 b16)
static __device__ __forceinline__ void ldsm4(uint32_t* r, uint32_t addr) {
    asm volatile(
        "ldmatrix.sync.aligned.m8n8.x4.shared.b16 {%0,%1,%2,%3}, [%4];"
        : "=r"(r[0]), "=r"(r[1]), "=r"(r[2]), "=r"(r[3]) : "r"(addr));
}
static __device__ __forceinline__ void cp16(uint32_t dst, const float* src) {
    asm volatile("cp.async.cg.shared.global [%0], [%1], 16;"
                 :: "r"(dst), "l"(src) : "memory");
}
static __device__ __forceinline__ void cp_commit() {
    asm volatile("cp.async.commit_group;" ::: "memory");
}
static __device__ __forceinline__ void cp_wait2() {
    asm volatile("cp.async.wait_group 2;" ::: "memory");
}

// ---------------- kernel 0: zero the per-expert counters -----------------
__global__ void k_zero_cnt() {
    if (threadIdx.x < NEXP) g_cnt[threadIdx.x] = 0;
}

// ---------------- kernel 1: router + identity out + tf32-round x ---------
__global__ void __launch_bounds__(128) k_router(
    const float* __restrict__ x,
    const float* __restrict__ cw,
    const float* __restrict__ bias,
    float* __restrict__ out)
{
    const int warp = threadIdx.x >> 5;
    const int lane = threadIdx.x & 31;
    const int t = blockIdx.x * 4 + warp;

    const float* xr = x + (size_t)t * HDIM;
    float* xq = g_xr + (size_t)t * HDIM;

    float acc[NTOT];
#pragma unroll
    for (int e = 0; e < NTOT; e++) acc[e] = 0.f;

    for (int h = lane; h < HDIM; h += 32) {
        const float xv = xr[h];
        xq[h] = __uint_as_float(to_tf32(xv));   // exact-tf32 copy for gemm1
#pragma unroll
        for (int e = 0; e < NTOT; e++)
            acc[e] = fmaf(xv, cw[e * HDIM + h], acc[e]);
    }
#pragma unroll
    for (int e = 0; e < NTOT; e++) {
#pragma unroll
        for (int o = 16; o > 0; o >>= 1)
            acc[e] += __shfl_xor_sync(0xFFFFFFFFu, acc[e], o);
    }

    float wid = 0.f;
    if (lane == 0) {
        float mx = acc[0];
#pragma unroll
        for (int e = 1; e < NTOT; e++) mx = fmaxf(mx, acc[e]);
        float p[NTOT], den = 0.f;
#pragma unroll
        for (int e = 0; e < NTOT; e++) { p[e] = __expf(acc[e] - mx); den += p[e]; }
        const float inv = 1.0f / den;

        float bv[NTOT];
#pragma unroll
        for (int e = 0; e < NTOT; e++) bv[e] = p[e] * inv + bias[e];

        int i0 = 0; float b0 = bv[0];
#pragma unroll
        for (int e = 1; e < NTOT; e++) if (bv[e] > b0) { b0 = bv[e]; i0 = e; }
        int i1 = -1; float b1 = -3.4e38f;
#pragma unroll
        for (int e = 0; e < NTOT; e++)
            if (e != i0 && bv[e] > b1) { b1 = bv[e]; i1 = e; }

        const int sel[2] = { i0, i1 };
#pragma unroll
        for (int k = 0; k < 2; k++) {
            const int   ie = sel[k];
            const float w  = p[ie] * inv * RSCALE;
            if (ie < NEXP) {
                const int s = atomicAdd(&g_cnt[ie], 1);
                g_tok[ie * TTOK + s] = t;
                g_wgt[ie * TTOK + s] = w;
            } else {
                wid += w;
            }
        }
    }
    wid = __shfl_sync(0xFFFFFFFFu, wid, 0);

    float* orow = out + (size_t)t * HDIM;
    for (int h = lane; h < HDIM; h += 32) orow[h] = xr[h] * wid;
}

// ================= kernel 2: gathered gate+up tf32 MMA + silu ============
// CTA tile: 128 tokens x 64 inter cols (gate & up), BK=32 cp.async 3-stage.
// A from g_xr (tf32-exact); B cvt.rna on fragments. Two-sync pipeline (R13).
__global__ void __launch_bounds__(256, 2) k_gemm1(
    const float* __restrict__ gate,
    const float* __restrict__ up)
{
    extern __shared__ __align__(16) float smemf[];
    int* tok_s = (int*)smemf;                 // 128 ints

    const int e   = blockIdx.z;
    const int cnt = g_cnt[e];
    const int r0  = blockIdx.y * 128;
    if (r0 >= cnt) return;
    const int n0  = blockIdx.x * 64;
    const int tid = threadIdx.x;

    if (tid < 128) {
        int r = r0 + tid;
        tok_s[tid] = g_tok[e * TTOK + (r < cnt ? r : cnt - 1)];
    }
    __syncthreads();

    // ---- async-copy setup ----
    const int cr  = tid >> 1;      // 0..127 (A row)
    const int chh = tid & 1;       // half-row (16 floats)
    const float* gA = g_xr + (size_t)tok_s[cr] * HDIM + chh * 16;

    const float* gB;
    uint32_t dB_off;
    {
        const int br = (tid & 127) >> 1;
        if (tid < 128) {
            gB = gate + ((size_t)e * IDIM + n0 + br) * HDIM + chh * 16;
            dB_off = 18432u + (uint32_t)br * 144u + (uint32_t)chh * 64u;
        } else {
            gB = up + ((size_t)e * IDIM + n0 + br) * HDIM + chh * 16;
            dB_off = 18432u + 9216u + (uint32_t)br * 144u + (uint32_t)chh * 64u;
        }
    }
    const uint32_t sb = smem_u32(smemf);
    const uint32_t dA = sb + 1024u + (uint32_t)cr * 144u + (uint32_t)chh * 64u;
    const uint32_t dB = sb + 1024u + dB_off;

    const int lane = tid & 31;
    const int wid  = tid >> 5;
    const int gid  = lane >> 2;
    const int tg   = lane & 3;
    const int wm   = (wid >> 2) * 64;
    const int wn   = (wid & 3) * 16;

    // ldmatrix per-thread address offsets (bytes, rel. to stage base)
    const int rit = lane & 7, til = lane >> 3;
    uint32_t offA[4], offBg, offBu;
#pragma unroll
    for (int mt = 0; mt < 4; mt++) {
        const int m_row = wm + mt * 16 + (til & 1) * 8 + rit;
        offA[mt] = 1024u + (uint32_t)(m_row * RS + (til >> 1) * 4) * 4u;
    }
    {
        const int n_row = wn + (til >> 1) * 8 + rit;
        offBg = 1024u + 18432u + (uint32_t)(n_row * RS + (til & 1) * 4) * 4u;
        offBu = offBg + 9216u;
    }

    float ag[4][2][4], au[4][2][4];
#pragma unroll
    for (int m = 0; m < 4; m++)
#pragma unroll
        for (int n = 0; n < 2; n++)
#pragma unroll
            for (int q = 0; q < 4; q++) { ag[m][n][q] = 0.f; au[m][n][q] = 0.f; }

#define G1_ISSUE(s, c) do {                                             \
        const float* pa = gA + (c) * BK;                                \
        const float* pb = gB + (c) * BK;                                \
        uint32_t da = dA + (uint32_t)(s) * STG_BYTES;                   \
        uint32_t db = dB + (uint32_t)(s) * STG_BYTES;                   \
        cp16(da +  0, pa + 0); cp16(da + 16, pa + 4);                   \
        cp16(da + 32, pa + 8); cp16(da + 48, pa + 12);                  \
        cp16(db +  0, pb + 0); cp16(db + 16, pb + 4);                   \
        cp16(db + 32, pb + 8); cp16(db + 48, pb + 12);                  \
    } while (0)

    G1_ISSUE(0, 0); cp_commit();
    G1_ISSUE(1, 1); cp_commit();

    const int NIT = HDIM / BK;   // 64
    for (int i = 0; i < NIT; i++) {
        if (i + 2 < NIT) G1_ISSUE((i + 2) % 3, i + 2);
        cp_commit();
        cp_wait2();
        __syncthreads();                 // all copies for stage i%3 visible

        const uint32_t stb = sb + (uint32_t)(i % 3) * STG_BYTES;
#pragma unroll
        for (int k8 = 0; k8 < BK; k8 += 8) {
            uint32_t bg[4], bu[4];
            ldsm4(bg, stb + offBg + (uint32_t)k8 * 4u);
            ldsm4(bu, stb + offBu + (uint32_t)k8 * 4u);
#pragma unroll
            for (int q = 0; q < 4; q++) { bg[q] = rnd_bits(bg[q]); bu[q] = rnd_bits(bu[q]); }
#pragma unroll
            for (int mt = 0; mt < 4; mt++) {
                uint32_t af[4];
                ldsm4(af, stb + offA[mt] + (uint32_t)k8 * 4u);
                mma_tf32(ag[mt][0], af, bg);
                mma_tf32(ag[mt][1], af, bg + 2);
                mma_tf32(au[mt][0], af, bu);
                mma_tf32(au[mt][1], af, bu + 2);
            }
        }
        __syncthreads();                 // all warps done before overwrite
    }

    // epilogue: silu(g)*u, RNA-rounded to tf32 -> g_act (gemm2's A is exact)
#pragma unroll
    for (int mt = 0; mt < 4; mt++) {
        const int sA = r0 + wm + mt * 16 + gid;
        const int sB = sA + 8;
#pragma unroll
        for (int nt = 0; nt < 2; nt++) {
            const int c = n0 + wn + nt * 8 + tg * 2;
            if (sA < cnt) {
                float gv0 = ag[mt][nt][0], gv1 = ag[mt][nt][1];
                float uv0 = au[mt][nt][0], uv1 = au[mt][nt][1];
                float2 o;
                o.x = __uint_as_float(to_tf32(gv0 / (1.f + __expf(-gv0)) * uv0));
                o.y = __uint_as_float(to_tf32(gv1 / (1.f + __expf(-gv1)) * uv1));
                *(float2*)&g_act[((size_t)e * TTOK + sA) * IDIM + c] = o;
            }
            if (sB < cnt) {
                float gv0 = ag[mt][nt][2], gv1 = ag[mt][nt][3];
                float uv0 = au[mt][nt][2], uv1 = au[mt][nt][3];
                float2 o;
                o.x = __uint_as_float(to_tf32(gv0 / (1.f + __expf(-gv0)) * uv0));
                o.y = __uint_as_float(to_tf32(gv1 / (1.f + __expf(-gv1)) * uv1));
                *(float2*)&g_act[((size_t)e * TTOK + sB) * IDIM + c] = o;
            }
        }
    }
#undef G1_ISSUE
}

// ================= kernel 3: down tf32 MMA + weighted scatter ============
// CTA tile: 128 slots x 128 h-cols, BK=32 cp.async 3-stage, two-sync (R13).
// A (g_act) is tf32-exact; B cvt.rna on fragments.
__global__ void __launch_bounds__(256, 2) k_gemm2(
    const float* __restrict__ down,
    float* __restrict__ out)
{
    extern __shared__ __align__(16) float smemf[];
    int*   tok_s = (int*)smemf;        // 128 ints
    float* w_s   = smemf + 128;        // 128 floats

    const int e   = blockIdx.z;
    const int cnt = g_cnt[e];
    const int r0  = blockIdx.y * 128;
    if (r0 >= cnt) return;
    const int n0  = blockIdx.x * 128;
    const int tid = threadIdx.x;

    if (tid < 128) {
        int r = r0 + tid;
        int rc = (r < cnt ? r : cnt - 1);
        tok_s[tid] = g_tok[e * TTOK + rc];
        w_s[tid]   = g_wgt[e * TTOK + rc];
    }
    __syncthreads();

    // ---- async-copy setup ----
    const int cr  = tid >> 1;
    const int chh = tid & 1;
    const int sc  = (r0 + cr < cnt) ? (r0 + cr) : (cnt - 1);
    const float* gA = g_act + ((size_t)e * TTOK + sc) * IDIM + chh * 16;
    const float* gB = down + (size_t)e * HDIM * IDIM
                    + (size_t)(n0 + cr) * IDIM + chh * 16;
    const uint32_t sb = smem_u32(smemf);
    const uint32_t dA = sb + 1024u + (uint32_t)cr * 144u + (uint32_t)chh * 64u;
    const uint32_t dB = dA + 18432u;

    const int lane = tid & 31;
    const int wid  = tid >> 5;
    const int gid  = lane >> 2;
    const int tg   = lane & 3;
    const int wm   = (wid >> 2) * 64;
    const int wn   = (wid & 3) * 32;

    const int rit = lane & 7, til = lane >> 3;
    uint32_t offA[4], offB[2];
#pragma unroll
    for (int mt = 0; mt < 4; mt++) {
        const int m_row = wm + mt * 16 + (til & 1) * 8 + rit;
        offA[mt] = 1024u + (uint32_t)(m_row * RS + (til >> 1) * 4) * 4u;
    }
#pragma unroll
    for (int p = 0; p < 2; p++) {
        const int n_row = wn + p * 16 + (til >> 1) * 8 + rit;
        offB[p] = 1024u + 18432u + (uint32_t)(n_row * RS + (til & 1) * 4) * 4u;
    }

    float acc[4][4][4];
#pragma unroll
    for (int m = 0; m < 4; m++)
#pragma unroll
        for (int n = 0; n < 4; n++)
#pragma unroll
            for (int q = 0; q < 4; q++) acc[m][n][q] = 0.f;

#define G2_ISSUE(s, c) do {                                             \
        const float* pa = gA + (c) * BK;                                \
        const float* pb = gB + (c) * BK;                                \
        uint32_t da = dA + (uint32_t)(s) * STG_BYTES;                   \
        uint32_t db = dB + (uint32_t)(s) * STG_BYTES;                   \
        cp16(da +  0, pa + 0); cp16(da + 16, pa + 4);                   \
        cp16(da + 32, pa + 8); cp16(da + 48, pa + 12);                  \
        cp16(db +  0, pb + 0); cp16(db + 16, pb + 4);                   \
        cp16(db + 32, pb + 8); cp16(db + 48, pb + 12);                  \
    } while (0)

    G2_ISSUE(0, 0); cp_commit();
    G2_ISSUE(1, 1); cp_commit();

    const int NIT = IDIM / BK;   // 32
    for (int i = 0; i < NIT; i++) {
        if (i + 2 < NIT) G2_ISSUE((i + 2) % 3, i + 2);
        cp_commit();
        cp_wait2();
        __syncthreads();

        const uint32_t stb = sb + (uint32_t)(i % 3) * STG_BYTES;
#pragma unroll
        for (int k8 = 0; k8 < BK; k8 += 8) {
            uint32_t b0[4], b1[4];
            ldsm4(b0, stb + offB[0] + (uint32_t)k8 * 4u);
            ldsm4(b1, stb + offB[1] + (uint32_t)k8 * 4u);
#pragma unroll
            for (int q = 0; q < 4; q++) { b0[q] = rnd_bits(b0[q]); b1[q] = rnd_bits(b1[q]); }
#pragma unroll
            for (int mt = 0; mt < 4; mt++) {
                uint32_t af[4];
                ldsm4(af, stb + offA[mt] + (uint32_t)k8 * 4u);
                mma_tf32(acc[mt][0], af, b0);
                mma_tf32(acc[mt][1], af, b0 + 2);
                mma_tf32(acc[mt][2], af, b1);
                mma_tf32(acc[mt][3], af, b1 + 2);
            }
        }
        __syncthreads();
    }

    // epilogue: weighted atomic scatter to out
#pragma unroll
    for (int mt = 0; mt < 4; mt++) {
        const int rowA = wm + mt * 16 + gid;
        const int rowB = rowA + 8;
        const int sA = r0 + rowA;
        const int sB = r0 + rowB;
#pragma unroll
        for (int nt = 0; nt < 4; nt++) {
            const int c = n0 + wn + nt * 8 + tg * 2;
            if (sA < cnt) {
                const float w = w_s[rowA];
                float* orow = out + (size_t)tok_s[rowA] * HDIM + c;
                atomicAdd(orow + 0, w * acc[mt][nt][0]);
                atomicAdd(orow + 1, w * acc[mt][nt][1]);
            }
            if (sB < cnt) {
                const float w = w_s[rowB];
                float* orow = out + (size_t)tok_s[rowB] * HDIM + c;
                atomicAdd(orow + 0, w * acc[mt][nt][2]);
                atomicAdd(orow + 1, w * acc[mt][nt][3]);
            }
        }
    }
#undef G2_ISSUE
}

// ---------------- launch ---------------------------------------------------
extern "C" void kernel_launch(void* const* d_in, const int* in_sizes, int n_in,
                              void* d_out, int out_size)
{
    (void)in_sizes; (void)n_in; (void)out_size;
    const float* x    = (const float*)d_in[0];   // [2,2048,2048]
    const float* cw   = (const float*)d_in[1];   // [12,2048]
    const float* bias = (const float*)d_in[2];   // [12]
    const float* gw   = (const float*)d_in[3];   // [8,1024,2048]
    const float* uw   = (const float*)d_in[4];   // [8,1024,2048]
    const float* dw   = (const float*)d_in[5];   // [8,2048,1024]
    float* out = (float*)d_out;                  // [2,2048,2048]

    cudaFuncSetAttribute(k_gemm1, cudaFuncAttributeMaxDynamicSharedMemorySize, SM_BYTES);
    cudaFuncSetAttribute(k_gemm2, cudaFuncAttributeMaxDynamicSharedMemorySize, SM_BYTES);

    k_zero_cnt<<<1, 32>>>();
    k_router<<<TTOK / 4, 128>>>(x, cw, bias, out);
    k_gemm1<<<dim3(IDIM / 64, TTOK / 128, NEXP), 256, SM_BYTES>>>(gw, uw);
    k_gemm2<<<dim3(HDIM / 128, TTOK / 128, NEXP), 256, SM_BYTES>>>(dw, out);
}

// round 16
// speedup vs baseline: 1.5971x; 1.5971x over previous
#include <cuda_runtime.h>
#include <cuda_fp16.h>
#include <cstdint>
#include <cstddef>

// Problem constants (fixed shapes)
#define HDIM   2048
#define IDIM   1024
#define TTOK   4096   // B*S
#define NEXP   8      // routed experts
#define NTOT   12     // routed + zero
#define RSCALE 1.5f

#define BK         64          // k-halfs per pipeline stage
#define RSH        72          // smem row stride in halfs (144 B) -> conflict-free
#define STG_BYTES  36864u
#define SM_BYTES   (1024 + 3 * 36864)   // header + 3 stages = 111616 B

// ---------------- device scratch (no allocations allowed) ----------------
__device__ int    g_cnt[NEXP];
__device__ int    g_tok[NEXP * TTOK];
__device__ float  g_wgt[NEXP * TTOK];
__device__ __half g_xh[(size_t)TTOK * HDIM];            // 16 MB fp16 x
__device__ __half g_acth[(size_t)NEXP * TTOK * IDIM];   // 64 MB fp16 act
__device__ __half g_gwh[(size_t)NEXP * IDIM * HDIM];    // 32 MB fp16 gate_w
__device__ __half g_uwh[(size_t)NEXP * IDIM * HDIM];    // 32 MB fp16 up_w
__device__ __half g_dwh[(size_t)NEXP * HDIM * IDIM];    // 32 MB fp16 down_w

// ---------------- helpers -------------------------------------------------
static __device__ __forceinline__ uint32_t smem_u32(const void* p) {
    uint32_t a;
    asm("{ .reg .u64 t; cvta.to.shared.u64 t, %1; cvt.u32.u64 %0, t; }"
        : "=r"(a) : "l"(p));
    return a;
}
// d += a(16x16 f16, row) * b(16x8 f16, col), f32 accumulate
static __device__ __forceinline__ void mma_f16(float* d, const uint32_t* a,
                                               const uint32_t* b) {
    asm volatile(
        "mma.sync.aligned.m16n8k16.row.col.f32.f16.f16.f32 "
        "{%0,%1,%2,%3}, {%4,%5,%6,%7}, {%8,%9}, {%0,%1,%2,%3};"
        : "+f"(d[0]), "+f"(d[1]), "+f"(d[2]), "+f"(d[3])
        : "r"(a[0]), "r"(a[1]), "r"(a[2]), "r"(a[3]), "r"(b[0]), "r"(b[1]));
}
static __device__ __forceinline__ void ldsm4(uint32_t* r, uint32_t addr) {
    asm volatile(
        "ldmatrix.sync.aligned.m8n8.x4.shared.b16 {%0,%1,%2,%3}, [%4];"
        : "=r"(r[0]), "=r"(r[1]), "=r"(r[2]), "=r"(r[3]) : "r"(addr));
}
static __device__ __forceinline__ void cp16(uint32_t dst, const void* src) {
    asm volatile("cp.async.cg.shared.global [%0], [%1], 16;"
                 :: "r"(dst), "l"(src) : "memory");
}
static __device__ __forceinline__ void cp_commit() {
    asm volatile("cp.async.commit_group;" ::: "memory");
}
static __device__ __forceinline__ void cp_wait2() {
    asm volatile("cp.async.wait_group 2;" ::: "memory");
}

// ---------------- kernel 0: zero the per-expert counters -----------------
__global__ void k_zero_cnt() {
    if (threadIdx.x < NEXP) g_cnt[threadIdx.x] = 0;
}

// ---------------- kernel 0b: fp16-convert the expert weights -------------
// 3 tensors x 16777216 elems; 8192 blocks each, 8 elems/thread.
__global__ void __launch_bounds__(256) k_cvtw(
    const float* __restrict__ gw,
    const float* __restrict__ uw,
    const float* __restrict__ dw)
{
    const int which = blockIdx.x >> 13;
    const float* src = (which == 0) ? gw : (which == 1) ? uw : dw;
    __half* dst = (which == 0) ? g_gwh : (which == 1) ? g_uwh : g_dwh;
    const size_t base = (((size_t)(blockIdx.x & 8191)) * 256 + threadIdx.x) * 8;
    const float4 v0 = *(const float4*)(src + base);
    const float4 v1 = *(const float4*)(src + base + 4);
    __half2 h[4];
    h[0] = __floats2half2_rn(v0.x, v0.y);
    h[1] = __floats2half2_rn(v0.z, v0.w);
    h[2] = __floats2half2_rn(v1.x, v1.y);
    h[3] = __floats2half2_rn(v1.z, v1.w);
    *(uint4*)(dst + base) = *(uint4*)h;
}

// ---------------- kernel 1: router + identity out + fp16 x ---------------
__global__ void __launch_bounds__(128) k_router(
    const float* __restrict__ x,
    const float* __restrict__ cw,
    const float* __restrict__ bias,
    float* __restrict__ out)
{
    const int warp = threadIdx.x >> 5;
    const int lane = threadIdx.x & 31;
    const int t = blockIdx.x * 4 + warp;

    const float* xr = x + (size_t)t * HDIM;
    __half* xq = g_xh + (size_t)t * HDIM;

    float acc[NTOT];
#pragma unroll
    for (int e = 0; e < NTOT; e++) acc[e] = 0.f;

    for (int h = lane; h < HDIM; h += 32) {
        const float xv = xr[h];
        xq[h] = __float2half_rn(xv);
#pragma unroll
        for (int e = 0; e < NTOT; e++)
            acc[e] = fmaf(xv, cw[e * HDIM + h], acc[e]);
    }
#pragma unroll
    for (int e = 0; e < NTOT; e++) {
#pragma unroll
        for (int o = 16; o > 0; o >>= 1)
            acc[e] += __shfl_xor_sync(0xFFFFFFFFu, acc[e], o);
    }

    float wid = 0.f;
    if (lane == 0) {
        float mx = acc[0];
#pragma unroll
        for (int e = 1; e < NTOT; e++) mx = fmaxf(mx, acc[e]);
        float p[NTOT], den = 0.f;
#pragma unroll
        for (int e = 0; e < NTOT; e++) { p[e] = __expf(acc[e] - mx); den += p[e]; }
        const float inv = 1.0f / den;

        float bv[NTOT];
#pragma unroll
        for (int e = 0; e < NTOT; e++) bv[e] = p[e] * inv + bias[e];

        int i0 = 0; float b0 = bv[0];
#pragma unroll
        for (int e = 1; e < NTOT; e++) if (bv[e] > b0) { b0 = bv[e]; i0 = e; }
        int i1 = -1; float b1 = -3.4e38f;
#pragma unroll
        for (int e = 0; e < NTOT; e++)
            if (e != i0 && bv[e] > b1) { b1 = bv[e]; i1 = e; }

        const int sel[2] = { i0, i1 };
#pragma unroll
        for (int k = 0; k < 2; k++) {
            const int   ie = sel[k];
            const float w  = p[ie] * inv * RSCALE;
            if (ie < NEXP) {
                const int s = atomicAdd(&g_cnt[ie], 1);
                g_tok[ie * TTOK + s] = t;
                g_wgt[ie * TTOK + s] = w;
            } else {
                wid += w;
            }
        }
    }
    wid = __shfl_sync(0xFFFFFFFFu, wid, 0);

    float* orow = out + (size_t)t * HDIM;
    for (int h = lane; h < HDIM; h += 32) orow[h] = xr[h] * wid;
}

// ================= kernel 2: gathered gate+up fp16 MMA + silu ============
// CTA tile: 128 tokens x 64 inter cols (gate & up), BK=64 halfs, 3-stage.
// Stage layout (bytes): A[128][72h]=18432 | Bg[64][72h]=9216 | Bu=9216.
__global__ void __launch_bounds__(256, 2) k_gemm1()
{
    extern __shared__ __align__(16) float smemf[];
    int* tok_s = (int*)smemf;                 // 128 ints

    const int e   = blockIdx.z;
    const int cnt = g_cnt[e];
    const int r0  = blockIdx.y * 128;
    if (r0 >= cnt) return;
    const int n0  = blockIdx.x * 64;
    const int tid = threadIdx.x;

    if (tid < 128) {
        int r = r0 + tid;
        tok_s[tid] = g_tok[e * TTOK + (r < cnt ? r : cnt - 1)];
    }
    __syncthreads();

    // ---- async-copy setup ----
    const int cr  = tid >> 1;      // 0..127 (A row)
    const int chh = tid & 1;       // half-row (32 halfs)
    const __half* gA = g_xh + (size_t)tok_s[cr] * HDIM + chh * 32;

    const __half* gB;
    uint32_t dB_off;
    {
        const int br = (tid & 127) >> 1;     // 0..63
        if (tid < 128) {
            gB = g_gwh + ((size_t)e * IDIM + n0 + br) * HDIM + chh * 32;
            dB_off = 18432u + (uint32_t)br * 144u + (uint32_t)chh * 64u;
        } else {
            gB = g_uwh + ((size_t)e * IDIM + n0 + br) * HDIM + chh * 32;
            dB_off = 18432u + 9216u + (uint32_t)br * 144u + (uint32_t)chh * 64u;
        }
    }
    const uint32_t sb = smem_u32(smemf);
    const uint32_t dA = sb + 1024u + (uint32_t)cr * 144u + (uint32_t)chh * 64u;
    const uint32_t dB = sb + 1024u + dB_off;

    const int lane = tid & 31;
    const int wid  = tid >> 5;
    const int gid  = lane >> 2;
    const int tg   = lane & 3;
    const int wm   = (wid >> 2) * 64;
    const int wn   = (wid & 3) * 16;

    // ldmatrix per-thread address offsets (bytes, rel. to stage base)
    const int rit = lane & 7, til = lane >> 3;
    uint32_t offA[4], offBg, offBu;
#pragma unroll
    for (int mt = 0; mt < 4; mt++) {
        const int m_row = wm + mt * 16 + (til & 1) * 8 + rit;
        offA[mt] = 1024u + (uint32_t)(m_row * RSH + (til >> 1) * 8) * 2u;
    }
    {
        const int n_row = wn + (til >> 1) * 8 + rit;
        offBg = 1024u + 18432u + (uint32_t)(n_row * RSH + (til & 1) * 8) * 2u;
        offBu = offBg + 9216u;
    }

    float ag[4][2][4], au[4][2][4];
#pragma unroll
    for (int m = 0; m < 4; m++)
#pragma unroll
        for (int n = 0; n < 2; n++)
#pragma unroll
            for (int q = 0; q < 4; q++) { ag[m][n][q] = 0.f; au[m][n][q] = 0.f; }

#define G1_ISSUE(s, c) do {                                             \
        const __half* pa = gA + (c) * BK;                               \
        const __half* pb = gB + (c) * BK;                               \
        uint32_t da = dA + (uint32_t)(s) * STG_BYTES;                   \
        uint32_t db = dB + (uint32_t)(s) * STG_BYTES;                   \
        cp16(da +  0, pa + 0);  cp16(da + 16, pa + 8);                  \
        cp16(da + 32, pa + 16); cp16(da + 48, pa + 24);                 \
        cp16(db +  0, pb + 0);  cp16(db + 16, pb + 8);                  \
        cp16(db + 32, pb + 16); cp16(db + 48, pb + 24);                 \
    } while (0)

    G1_ISSUE(0, 0); cp_commit();
    G1_ISSUE(1, 1); cp_commit();

    const int NIT = HDIM / BK;   // 32
    for (int i = 0; i < NIT; i++) {
        if (i + 2 < NIT) G1_ISSUE((i + 2) % 3, i + 2);
        cp_commit();
        cp_wait2();
        __syncthreads();                 // copies for stage i%3 visible

        const uint32_t stb = sb + (uint32_t)(i % 3) * STG_BYTES;
#pragma unroll
        for (int s = 0; s < 4; s++) {    // 4 k16-steps
            uint32_t bg[4], bu[4];
            ldsm4(bg, stb + offBg + (uint32_t)s * 32u);
            ldsm4(bu, stb + offBu + (uint32_t)s * 32u);
#pragma unroll
            for (int mt = 0; mt < 4; mt++) {
                uint32_t af[4];
                ldsm4(af, stb + offA[mt] + (uint32_t)s * 32u);
                mma_f16(ag[mt][0], af, bg);
                mma_f16(ag[mt][1], af, bg + 2);
                mma_f16(au[mt][0], af, bu);
                mma_f16(au[mt][1], af, bu + 2);
            }
        }
        __syncthreads();                 // all warps done before overwrite
    }

    // epilogue: silu(g)*u, RNA-rounded to fp16 -> g_acth
#pragma unroll
    for (int mt = 0; mt < 4; mt++) {
        const int sA = r0 + wm + mt * 16 + gid;
        const int sB = sA + 8;
#pragma unroll
        for (int nt = 0; nt < 2; nt++) {
            const int c = n0 + wn + nt * 8 + tg * 2;
            if (sA < cnt) {
                float gv0 = ag[mt][nt][0], gv1 = ag[mt][nt][1];
                float uv0 = au[mt][nt][0], uv1 = au[mt][nt][1];
                __half2 hv = __floats2half2_rn(
                    gv0 / (1.f + __expf(-gv0)) * uv0,
                    gv1 / (1.f + __expf(-gv1)) * uv1);
                *(__half2*)&g_acth[((size_t)e * TTOK + sA) * IDIM + c] = hv;
            }
            if (sB < cnt) {
                float gv0 = ag[mt][nt][2], gv1 = ag[mt][nt][3];
                float uv0 = au[mt][nt][2], uv1 = au[mt][nt][3];
                __half2 hv = __floats2half2_rn(
                    gv0 / (1.f + __expf(-gv0)) * uv0,
                    gv1 / (1.f + __expf(-gv1)) * uv1);
                *(__half2*)&g_acth[((size_t)e * TTOK + sB) * IDIM + c] = hv;
            }
        }
    }
#undef G1_ISSUE
}

// ================= kernel 3: down fp16 MMA + weighted scatter ============
// CTA tile: 128 slots x 128 h-cols, BK=64 halfs, 3-stage.
// Stage layout: A[128][72h]=18432 | B[128][72h]=18432.
__global__ void __launch_bounds__(256, 2) k_gemm2(float* __restrict__ out)
{
    extern __shared__ __align__(16) float smemf[];
    int*   tok_s = (int*)smemf;        // 128 ints
    float* w_s   = smemf + 128;        // 128 floats

    const int e   = blockIdx.z;
    const int cnt = g_cnt[e];
    const int r0  = blockIdx.y * 128;
    if (r0 >= cnt) return;
    const int n0  = blockIdx.x * 128;
    const int tid = threadIdx.x;

    if (tid < 128) {
        int r = r0 + tid;
        int rc = (r < cnt ? r : cnt - 1);
        tok_s[tid] = g_tok[e * TTOK + rc];
        w_s[tid]   = g_wgt[e * TTOK + rc];
    }
    __syncthreads();

    // ---- async-copy setup ----
    const int cr  = tid >> 1;
    const int chh = tid & 1;
    const int sc  = (r0 + cr < cnt) ? (r0 + cr) : (cnt - 1);
    const __half* gA = g_acth + ((size_t)e * TTOK + sc) * IDIM + chh * 32;
    const __half* gB = g_dwh + (size_t)e * HDIM * IDIM
                     + (size_t)(n0 + cr) * IDIM + chh * 32;
    const uint32_t sb = smem_u32(smemf);
    const uint32_t dA = sb + 1024u + (uint32_t)cr * 144u + (uint32_t)chh * 64u;
    const uint32_t dB = dA + 18432u;

    const int lane = tid & 31;
    const int wid  = tid >> 5;
    const int gid  = lane >> 2;
    const int tg   = lane & 3;
    const int wm   = (wid >> 2) * 64;
    const int wn   = (wid & 3) * 32;

    const int rit = lane & 7, til = lane >> 3;
    uint32_t offA[4], offB[2];
#pragma unroll
    for (int mt = 0; mt < 4; mt++) {
        const int m_row = wm + mt * 16 + (til & 1) * 8 + rit;
        offA[mt] = 1024u + (uint32_t)(m_row * RSH + (til >> 1) * 8) * 2u;
    }
#pragma unroll
    for (int p = 0; p < 2; p++) {
        const int n_row = wn + p * 16 + (til >> 1) * 8 + rit;
        offB[p] = 1024u + 18432u + (uint32_t)(n_row * RSH + (til & 1) * 8) * 2u;
    }

    float acc[4][4][4];
#pragma unroll
    for (int m = 0; m < 4; m++)
#pragma unroll
        for (int n = 0; n < 4; n++)
#pragma unroll
            for (int q = 0; q < 4; q++) acc[m][n][q] = 0.f;

#define G2_ISSUE(s, c) do {                                             \
        const __half* pa = gA + (c) * BK;                               \
        const __half* pb = gB + (c) * BK;                               \
        uint32_t da = dA + (uint32_t)(s) * STG_BYTES;                   \
        uint32_t db = dB + (uint32_t)(s) * STG_BYTES;                   \
        cp16(da +  0, pa + 0);  cp16(da + 16, pa + 8);                  \
        cp16(da + 32, pa + 16); cp16(da + 48, pa + 24);                 \
        cp16(db +  0, pb + 0);  cp16(db + 16, pb + 8);                  \
        cp16(db + 32, pb + 16); cp16(db + 48, pb + 24);                 \
    } while (0)

    G2_ISSUE(0, 0); cp_commit();
    G2_ISSUE(1, 1); cp_commit();

    const int NIT = IDIM / BK;   // 16
    for (int i = 0; i < NIT; i++) {
        if (i + 2 < NIT) G2_ISSUE((i + 2) % 3, i + 2);
        cp_commit();
        cp_wait2();
        __syncthreads();

        const uint32_t stb = sb + (uint32_t)(i % 3) * STG_BYTES;
#pragma unroll
        for (int s = 0; s < 4; s++) {    // 4 k16-steps
            uint32_t b01[4], b23[4];
            ldsm4(b01, stb + offB[0] + (uint32_t)s * 32u);
            ldsm4(b23, stb + offB[1] + (uint32_t)s * 32u);
#pragma unroll
            for (int mt = 0; mt < 4; mt++) {
                uint32_t af[4];
                ldsm4(af, stb + offA[mt] + (uint32_t)s * 32u);
                mma_f16(acc[mt][0], af, b01);
                mma_f16(acc[mt][1], af, b01 + 2);
                mma_f16(acc[mt][2], af, b23);
                mma_f16(acc[mt][3], af, b23 + 2);
            }
        }
        __syncthreads();
    }

    // epilogue: weighted atomic scatter to out
#pragma unroll
    for (int mt = 0; mt < 4; mt++) {
        const int rowA = wm + mt * 16 + gid;
        const int rowB = rowA + 8;
        const int sA = r0 + rowA;
        const int sB = r0 + rowB;
#pragma unroll
        for (int nt = 0; nt < 4; nt++) {
            const int c = n0 + wn + nt * 8 + tg * 2;
            if (sA < cnt) {
                const float w = w_s[rowA];
                float* orow = out + (size_t)tok_s[rowA] * HDIM + c;
                atomicAdd(orow + 0, w * acc[mt][nt][0]);
                atomicAdd(orow + 1, w * acc[mt][nt][1]);
            }
            if (sB < cnt) {
                const float w = w_s[rowB];
                float* orow = out + (size_t)tok_s[rowB] * HDIM + c;
                atomicAdd(orow + 0, w * acc[mt][nt][2]);
                atomicAdd(orow + 1, w * acc[mt][nt][3]);
            }
        }
    }
#undef G2_ISSUE
}

// ---------------- launch ---------------------------------------------------
extern "C" void kernel_launch(void* const* d_in, const int* in_sizes, int n_in,
                              void* d_out, int out_size)
{
    (void)in_sizes; (void)n_in; (void)out_size;
    const float* x    = (const float*)d_in[0];   // [2,2048,2048]
    const float* cw   = (const float*)d_in[1];   // [12,2048]
    const float* bias = (const float*)d_in[2];   // [12]
    const float* gw   = (const float*)d_in[3];   // [8,1024,2048]
    const float* uw   = (const float*)d_in[4];   // [8,1024,2048]
    const float* dw   = (const float*)d_in[5];   // [8,2048,1024]
    float* out = (float*)d_out;                  // [2,2048,2048]

    cudaFuncSetAttribute(k_gemm1, cudaFuncAttributeMaxDynamicSharedMemorySize, SM_BYTES);
    cudaFuncSetAttribute(k_gemm2, cudaFuncAttributeMaxDynamicSharedMemorySize, SM_BYTES);

    k_zero_cnt<<<1, 32>>>();
    k_cvtw<<<3 * 8192, 256>>>(gw, uw, dw);
    k_router<<<TTOK / 4, 128>>>(x, cw, bias, out);
    k_gemm1<<<dim3(IDIM / 64, TTOK / 128, NEXP), 256, SM_BYTES>>>();
    k_gemm2<<<dim3(HDIM / 128, TTOK / 128, NEXP), 256, SM_BYTES>>>(out);
}